// round 6
// baseline (speedup 1.0000x reference)
#include <cuda_runtime.h>
#include <cuda_fp16.h>
#include <cstdint>

#define NN 50000
#define EE 800000
#define HH 8
#define HD 128
#define CCOLS 40
#define CSR_BLOCKS 148
#define CSR_THREADS 1024
#define CSR_CH 338           // ceil(NN / CSR_BLOCKS)

// ---------------- scratch -------------------------------------------------
__device__ __half g_hp[NN * HD];     // fp16 projected features (gather payload)
__device__ float  g_hbuf[NN * HD];   // layer output / next-layer input (fp32)
__device__ float  g_el[NN * HH];
__device__ float  g_er[NN * HH];
__device__ int    g_rowptr[NN + 1];
__device__ int    g_wr[NN];
__device__ int    g_csrc[EE];
__device__ int    g_bsum[CSR_BLOCKS];
__device__ unsigned int g_sync = 0;

// ---------------- single-kernel CSR build with grid barrier -----------------
__device__ __forceinline__ void gsync(unsigned target) {
    __threadfence();           // release (gpu scope)
    __syncthreads();
    if (threadIdx.x == 0) {
        atomicAdd(&g_sync, 1u);
        while (*(volatile unsigned*)&g_sync < target) { __nanosleep(40); }
    }
    __syncthreads();
    __threadfence();           // acquire
}

__device__ __forceinline__ int block_excl_scan1024(int v, int& total) {
    __shared__ int wsum[33];
    int lane = threadIdx.x & 31, wid = threadIdx.x >> 5;
    int x = v;
    #pragma unroll
    for (int off = 1; off < 32; off <<= 1) {
        int y = __shfl_up_sync(0xFFFFFFFFu, x, off);
        if (lane >= off) x += y;
    }
    if (lane == 31) wsum[wid] = x;
    __syncthreads();
    if (wid == 0) {
        int w = wsum[lane];
        int xw = w;
        #pragma unroll
        for (int off = 1; off < 32; off <<= 1) {
            int y = __shfl_up_sync(0xFFFFFFFFu, xw, off);
            if (lane >= off) xw += y;
        }
        wsum[lane] = xw - w;
        if (lane == 31) wsum[32] = xw;
    }
    __syncthreads();
    int res = wsum[wid] + x - v;
    total = wsum[32];
    __syncthreads();
    return res;
}

__global__ __launch_bounds__(CSR_THREADS, 1) void csr_build_kernel(
    const int* __restrict__ src, const int* __restrict__ dst) {
    const int gtid = blockIdx.x * CSR_THREADS + threadIdx.x;
    const int GT = CSR_BLOCKS * CSR_THREADS;          // 151552

    // P1: zero counters
    for (int i = gtid; i < NN; i += GT) g_wr[i] = 0;
    gsync(1u * CSR_BLOCKS);

    // P2: count degrees (int4 = 4 edges per iter)
    for (int i = gtid; i < EE / 4; i += GT) {
        int4 d = ((const int4*)dst)[i];
        atomicAdd(&g_wr[d.x], 1);
        atomicAdd(&g_wr[d.y], 1);
        atomicAdd(&g_wr[d.z], 1);
        atomicAdd(&g_wr[d.w], 1);
    }
    gsync(2u * CSR_BLOCKS);

    // P3: per-block chunk scan
    int c0 = blockIdx.x * CSR_CH;
    int cnt = NN - c0; if (cnt < 0) cnt = 0; if (cnt > CSR_CH) cnt = CSR_CH;
    {
        int t = threadIdx.x;
        int v = (t < cnt) ? g_wr[c0 + t] : 0;
        int total;
        int excl = block_excl_scan1024(v, total);
        if (t < cnt) g_rowptr[c0 + t] = excl;
        if (t == 0) g_bsum[blockIdx.x] = total;
    }
    gsync(3u * CSR_BLOCKS);

    // P4: block 0 scans block totals
    if (blockIdx.x == 0) {
        int t = threadIdx.x;
        int v = (t < CSR_BLOCKS) ? g_bsum[t] : 0;
        int total;
        int excl = block_excl_scan1024(v, total);
        if (t < CSR_BLOCKS) g_bsum[t] = excl;
        if (t == 0) g_rowptr[NN] = EE;
    }
    gsync(4u * CSR_BLOCKS);

    // P5: add block offsets, init write cursors
    {
        int off = g_bsum[blockIdx.x];
        int t = threadIdx.x;
        if (t < cnt) {
            int v = g_rowptr[c0 + t] + off;
            g_rowptr[c0 + t] = v;
            g_wr[c0 + t] = v;
        }
    }
    gsync(5u * CSR_BLOCKS);

    // P6: scatter src ids into CSR
    for (int i = gtid; i < EE / 4; i += GT) {
        int4 d = ((const int4*)dst)[i];
        int4 s = ((const int4*)src)[i];
        g_csrc[atomicAdd(&g_wr[d.x], 1)] = s.x;
        g_csrc[atomicAdd(&g_wr[d.y], 1)] = s.y;
        g_csrc[atomicAdd(&g_wr[d.z], 1)] = s.z;
        g_csrc[atomicAdd(&g_wr[d.w], 1)] = s.w;
    }

    // exit: last block out resets the barrier counter for the next replay
    __syncthreads();
    if (threadIdx.x == 0) {
        unsigned old = atomicAdd(&g_sync, 1u);
        if (old == 6u * CSR_BLOCKS - 1u) *(volatile unsigned*)&g_sync = 0u;
    }
}

// ---------------- TF32 GEMM + fused el/er epilogue, fp16 C ------------------
__device__ __forceinline__ uint32_t f2tf32(float x) {
    uint32_t r;
    asm("cvt.rna.tf32.f32 %0, %1;" : "=r"(r) : "f"(x));
    return r;
}

__device__ __forceinline__ void mma_tf32(float* c, const uint32_t* a,
                                         uint32_t b0, uint32_t b1) {
    asm volatile(
        "mma.sync.aligned.m16n8k8.row.col.f32.tf32.tf32.f32 "
        "{%0,%1,%2,%3}, {%4,%5,%6,%7}, {%8,%9}, {%0,%1,%2,%3};"
        : "+f"(c[0]), "+f"(c[1]), "+f"(c[2]), "+f"(c[3])
        : "r"(a[0]), "r"(a[1]), "r"(a[2]), "r"(a[3]), "r"(b0), "r"(b1));
}

__global__ __launch_bounds__(256) void gemm_tf32_kernel(
    const float* __restrict__ A, const float* __restrict__ W, __half* __restrict__ C,
    const float* __restrict__ al, const float* __restrict__ ar) {
    __shared__ uint32_t As[64][36];
    __shared__ uint32_t Wsh[32][136];
    __shared__ float s_el[64][8];
    __shared__ float s_er[64][8];
    int tid = threadIdx.x;
    int wid = tid >> 5;
    int lane = tid & 31;
    int g = lane >> 2;
    int tig = lane & 3;
    int warpRow = wid & 1;
    int warpCol = wid >> 1;
    int row0 = blockIdx.x << 6;

    float c[2][4][4];
    #pragma unroll
    for (int sm = 0; sm < 2; sm++)
        #pragma unroll
        for (int sn = 0; sn < 4; sn++)
            #pragma unroll
            for (int q = 0; q < 4; q++) c[sm][sn][q] = 0.f;

    for (int kc = 0; kc < 128; kc += 32) {
        #pragma unroll
        for (int q = 0; q < 2; q++) {
            int lin = tid + (q << 8);
            int r = lin >> 3;
            int k4 = lin & 7;
            int gr = row0 + r;
            float4 v = (gr < NN) ? *(const float4*)&A[gr * 128 + kc + k4 * 4]
                                 : make_float4(0.f, 0.f, 0.f, 0.f);
            uint32_t* p = &As[r][k4 * 4];
            p[0] = f2tf32(v.x); p[1] = f2tf32(v.y);
            p[2] = f2tf32(v.z); p[3] = f2tf32(v.w);
        }
        #pragma unroll
        for (int q = 0; q < 4; q++) {
            int lin = tid + (q << 8);
            int k = lin >> 5;
            int c4 = lin & 31;
            float4 v = *(const float4*)&W[(kc + k) * 128 + c4 * 4];
            uint32_t* p = &Wsh[k][c4 * 4];
            p[0] = f2tf32(v.x); p[1] = f2tf32(v.y);
            p[2] = f2tf32(v.z); p[3] = f2tf32(v.w);
        }
        __syncthreads();
        #pragma unroll
        for (int kk = 0; kk < 32; kk += 8) {
            uint32_t a[2][4];
            #pragma unroll
            for (int sm = 0; sm < 2; sm++) {
                int r = warpRow * 32 + sm * 16 + g;
                a[sm][0] = As[r][kk + tig];
                a[sm][1] = As[r + 8][kk + tig];
                a[sm][2] = As[r][kk + tig + 4];
                a[sm][3] = As[r + 8][kk + tig + 4];
            }
            #pragma unroll
            for (int sn = 0; sn < 4; sn++) {
                int cix = warpCol * 32 + sn * 8 + g;
                uint32_t b0 = Wsh[kk + tig][cix];
                uint32_t b1 = Wsh[kk + tig + 4][cix];
                mma_tf32(c[0][sn], a[0], b0, b1);
                mma_tf32(c[1][sn], a[1], b0, b1);
            }
        }
        __syncthreads();
    }

    // ---- store C (fp16) + compute el/er ----
    float alr[4][2], arr[4][2];
    #pragma unroll
    for (int sn = 0; sn < 4; sn++) {
        int col = warpCol * 32 + sn * 8 + tig * 2;
        alr[sn][0] = al[col];     alr[sn][1] = al[col + 1];
        arr[sn][0] = ar[col];     arr[sn][1] = ar[col + 1];
    }
    #pragma unroll
    for (int sm = 0; sm < 2; sm++) {
        int rbase = row0 + warpRow * 32 + sm * 16 + g;
        #pragma unroll
        for (int sn = 0; sn < 4; sn++) {
            int col = warpCol * 32 + sn * 8 + tig * 2;
            if (rbase < NN)
                *(__half2*)&C[rbase * 128 + col] =
                    __floats2half2_rn(c[sm][sn][0], c[sm][sn][1]);
            if (rbase + 8 < NN)
                *(__half2*)&C[(rbase + 8) * 128 + col] =
                    __floats2half2_rn(c[sm][sn][2], c[sm][sn][3]);
        }
        #pragma unroll
        for (int hh = 0; hh < 2; hh++) {
            #pragma unroll
            for (int ro = 0; ro < 2; ro++) {
                float pel = 0.f, per = 0.f;
                #pragma unroll
                for (int sni = 0; sni < 2; sni++) {
                    int sn = hh * 2 + sni;
                    #pragma unroll
                    for (int qq = 0; qq < 2; qq++) {
                        float cv = c[sm][sn][ro * 2 + qq];
                        pel = fmaf(cv, alr[sn][qq], pel);
                        per = fmaf(cv, arr[sn][qq], per);
                    }
                }
                pel += __shfl_xor_sync(0xFFFFFFFFu, pel, 1);
                pel += __shfl_xor_sync(0xFFFFFFFFu, pel, 2);
                per += __shfl_xor_sync(0xFFFFFFFFu, per, 1);
                per += __shfl_xor_sync(0xFFFFFFFFu, per, 2);
                if (tig == 0) {
                    int r = warpRow * 32 + sm * 16 + g + ro * 8;
                    int h = warpCol * 2 + hh;
                    s_el[r][h] = pel;
                    s_er[r][h] = per;
                }
            }
        }
    }
    __syncthreads();
    #pragma unroll
    for (int q = 0; q < 2; q++) {
        int idx = tid + (q << 8);
        int r = idx >> 3, h = idx & 7;
        if (row0 + r < NN) {
            g_el[(row0 + r) * 8 + h] = s_el[r][h];
            g_er[(row0 + r) * 8 + h] = s_er[r][h];
        }
    }
}

// ---------------- fused: edge-softmax aggregate + bias + LN + ReLU ----------
__global__ __launch_bounds__(256) void gat_agg_kernel(
    const __half* __restrict__ hp,
    const float* __restrict__ bias, const float* __restrict__ gamma,
    const float* __restrict__ beta, float* __restrict__ hout) {
    int n = blockIdx.x * 8 + (threadIdx.x >> 5);
    if (n >= NN) return;
    int lane = threadIdx.x & 31;
    int h = lane >> 2;
    float er_h = g_er[n * 8 + h];
    int beg = g_rowptr[n];
    int end = g_rowptr[n + 1];
    const uint2* __restrict__ hp2 = (const uint2*)hp;  // 4 halves per lane

    float ax = 0.f, ay = 0.f, az = 0.f, aw = 0.f, s = 0.f;
    int j = beg;
    for (; j + 8 <= end; j += 8) {
        int idx[8];
        #pragma unroll
        for (int u = 0; u < 8; u++) idx[u] = g_csrc[j + u];
        float e[8];
        #pragma unroll
        for (int u = 0; u < 8; u++) e[u] = g_el[idx[u] * 8 + h];
        uint2 v[8];
        #pragma unroll
        for (int u = 0; u < 8; u++) v[u] = hp2[idx[u] * 32 + lane];
        #pragma unroll
        for (int u = 0; u < 8; u++) {
            float ee = e[u] + er_h;
            ee = (ee > 0.f) ? ee : 0.2f * ee;
            float w = __expf(ee);
            s += w;
            float2 f0 = __half22float2(*(__half2*)&v[u].x);
            float2 f1 = __half22float2(*(__half2*)&v[u].y);
            ax = fmaf(w, f0.x, ax);
            ay = fmaf(w, f0.y, ay);
            az = fmaf(w, f1.x, az);
            aw = fmaf(w, f1.y, aw);
        }
    }
    for (; j + 4 <= end; j += 4) {
        int idx[4];
        #pragma unroll
        for (int u = 0; u < 4; u++) idx[u] = g_csrc[j + u];
        float e[4];
        #pragma unroll
        for (int u = 0; u < 4; u++) e[u] = g_el[idx[u] * 8 + h];
        uint2 v[4];
        #pragma unroll
        for (int u = 0; u < 4; u++) v[u] = hp2[idx[u] * 32 + lane];
        #pragma unroll
        for (int u = 0; u < 4; u++) {
            float ee = e[u] + er_h;
            ee = (ee > 0.f) ? ee : 0.2f * ee;
            float w = __expf(ee);
            s += w;
            float2 f0 = __half22float2(*(__half2*)&v[u].x);
            float2 f1 = __half22float2(*(__half2*)&v[u].y);
            ax = fmaf(w, f0.x, ax);
            ay = fmaf(w, f0.y, ay);
            az = fmaf(w, f1.x, az);
            aw = fmaf(w, f1.y, aw);
        }
    }
    for (; j < end; j++) {
        int s0 = g_csrc[j];
        float e0 = g_el[s0 * 8 + h] + er_h;
        e0 = (e0 > 0.f) ? e0 : 0.2f * e0;
        float w0 = __expf(e0);
        uint2 v0 = hp2[s0 * 32 + lane];
        s += w0;
        float2 f0 = __half22float2(*(__half2*)&v0.x);
        float2 f1 = __half22float2(*(__half2*)&v0.y);
        ax = fmaf(w0, f0.x, ax);
        ay = fmaf(w0, f0.y, ay);
        az = fmaf(w0, f1.x, az);
        aw = fmaf(w0, f1.y, aw);
    }

    float inv = 1.f / (s + 1e-16f);
    float4 b4  = ((const float4*)bias)[lane];
    float4 g4  = ((const float4*)gamma)[lane];
    float4 be4 = ((const float4*)beta)[lane];
    float ox = fmaf(ax, inv, b4.x);
    float oy = fmaf(ay, inv, b4.y);
    float oz = fmaf(az, inv, b4.z);
    float ow = fmaf(aw, inv, b4.w);

    float sum = (ox + oy) + (oz + ow);
    #pragma unroll
    for (int off = 16; off >= 1; off >>= 1) sum += __shfl_xor_sync(0xFFFFFFFFu, sum, off);
    float mu = sum * 0.0078125f;
    float dx = ox - mu, dy = oy - mu, dz = oz - mu, dw = ow - mu;
    float sq = (dx * dx + dy * dy) + (dz * dz + dw * dw);
    #pragma unroll
    for (int off = 16; off >= 1; off >>= 1) sq += __shfl_xor_sync(0xFFFFFFFFu, sq, off);
    float rstd = rsqrtf(sq * 0.0078125f + 1e-5f);
    float4 o;
    o.x = fmaxf(fmaf(dx * rstd, g4.x, be4.x), 0.f);
    o.y = fmaxf(fmaf(dy * rstd, g4.y, be4.y), 0.f);
    o.z = fmaxf(fmaf(dz * rstd, g4.z, be4.z), 0.f);
    o.w = fmaxf(fmaf(dw * rstd, g4.w, be4.w), 0.f);
    ((float4*)hout)[n * 32 + lane] = o;
}

// ---------------- final projection: out[N,40] = h[N,128] @ Wp + bp ----------
__global__ __launch_bounds__(160) void pred_kernel(
    const float* __restrict__ hfeat, const float* __restrict__ Wp,
    const float* __restrict__ bp, float* __restrict__ out) {
    __shared__ float Hs[64][68];
    __shared__ float Wsh[64][40];
    int tid = threadIdx.x;
    int ci = tid % 10;
    int j  = tid / 10;
    int n0 = blockIdx.x << 6;
    float acc[4][4];
    #pragma unroll
    for (int r = 0; r < 4; r++)
        #pragma unroll
        for (int c = 0; c < 4; c++) acc[r][c] = 0.f;

    for (int kc = 0; kc < 128; kc += 64) {
        for (int idx = tid; idx < 64 * 64; idx += 160) {
            int n = idx >> 6;
            int k = idx & 63;
            int gn = n0 + n;
            Hs[k][n] = (gn < NN) ? hfeat[gn * 128 + kc + k] : 0.f;
        }
        for (int idx = tid; idx < 64 * 40; idx += 160) {
            int k = idx / 40;
            int c = idx - k * 40;
            Wsh[k][c] = Wp[(kc + k) * 40 + c];
        }
        __syncthreads();
        #pragma unroll
        for (int k = 0; k < 64; k++) {
            float4 a = *(const float4*)&Hs[k][j * 4];
            float4 b = *(const float4*)&Wsh[k][ci * 4];
            float av[4] = {a.x, a.y, a.z, a.w};
            float bv[4] = {b.x, b.y, b.z, b.w};
            #pragma unroll
            for (int r = 0; r < 4; r++)
                #pragma unroll
                for (int c = 0; c < 4; c++)
                    acc[r][c] = fmaf(av[r], bv[c], acc[r][c]);
        }
        __syncthreads();
    }
    #pragma unroll
    for (int r = 0; r < 4; r++) {
        int gn = n0 + j * 4 + r;
        if (gn < NN) {
            #pragma unroll
            for (int c = 0; c < 4; c++)
                out[gn * CCOLS + ci * 4 + c] = acc[r][c] + bp[ci * 4 + c];
        }
    }
}

// ---------------- launch ----------------------------------------------------
extern "C" void kernel_launch(void* const* d_in, const int* in_sizes, int n_in,
                              void* d_out, int out_size) {
    const float* feats = (const float*)d_in[0];
    const int*   src   = (const int*)d_in[1];
    const int*   dst   = (const int*)d_in[2];
    const float* Ws    = (const float*)d_in[3];
    const float* al    = (const float*)d_in[4];
    const float* ar    = (const float*)d_in[5];
    const float* bias  = (const float*)d_in[6];
    const float* gamma = (const float*)d_in[7];
    const float* beta  = (const float*)d_in[8];
    const float* Wp    = (const float*)d_in[9];
    const float* bp    = (const float*)d_in[10];
    float* out = (float*)d_out;

    __half* hp;  cudaGetSymbolAddress((void**)&hp, g_hp);
    float* hbuf; cudaGetSymbolAddress((void**)&hbuf, g_hbuf);

    // serial: CSR build runs ALONE (a grid-wide spin kernel is a bad co-tenant)
    csr_build_kernel<<<CSR_BLOCKS, CSR_THREADS>>>(src, dst);

    const int gemm_blocks = (NN + 63) / 64;  // 782
    gemm_tf32_kernel<<<gemm_blocks, 256>>>(feats, Ws, hp, al, ar);
    gat_agg_kernel<<<(NN + 7) / 8, 256>>>(hp, bias, gamma, beta, hbuf);

    gemm_tf32_kernel<<<gemm_blocks, 256>>>(hbuf, Ws + 128 * 128, hp,
                                           al + 128, ar + 128);
    gat_agg_kernel<<<(NN + 7) / 8, 256>>>(hp, bias + 128, gamma + 128,
                                          beta + 128, hbuf);

    pred_kernel<<<gemm_blocks, 160>>>(hbuf, Wp, bp, out);
}

// round 7
// speedup vs baseline: 1.0841x; 1.0841x over previous
#include <cuda_runtime.h>
#include <cuda_fp16.h>
#include <cstdint>

#define NN 50000
#define EE 800000
#define HH 8
#define HD 128
#define CCOLS 40
#define SCAN_NBLK 49   // ceil(50000/1024)

// ---------------- scratch -------------------------------------------------
__device__ __half g_hp[NN * HD];     // fp16 projected features (gather payload)
__device__ float  g_hbuf[NN * HD];   // layer output / next-layer input (fp32)
__device__ float  g_el[NN * HH];
__device__ float  g_er[NN * HH];
__device__ int    g_rowptr[NN + 1];
__device__ int    g_wr[NN];
__device__ int    g_csrc[EE];
__device__ int    g_bsum[64];

// ---------------- CSR build (6-kernel pipeline, measured-good) --------------
__global__ void zero_wr_kernel() {
    int i = blockIdx.x * blockDim.x + threadIdx.x;
    if (i < NN) g_wr[i] = 0;
}

__global__ void count_deg_kernel(const int* __restrict__ dst) {
    int e4 = blockIdx.x * blockDim.x + threadIdx.x;
    if (e4 * 4 < EE) {
        int4 d = ((const int4*)dst)[e4];
        atomicAdd(&g_wr[d.x], 1);
        atomicAdd(&g_wr[d.y], 1);
        atomicAdd(&g_wr[d.z], 1);
        atomicAdd(&g_wr[d.w], 1);
    }
}

__global__ __launch_bounds__(1024) void scan1_kernel() {
    __shared__ int wsum[32];
    int t = threadIdx.x;
    int lane = t & 31, wid = t >> 5;
    int i = blockIdx.x * 1024 + t;
    int v = (i < NN) ? g_wr[i] : 0;
    int x = v;
    #pragma unroll
    for (int off = 1; off < 32; off <<= 1) {
        int y = __shfl_up_sync(0xFFFFFFFFu, x, off);
        if (lane >= off) x += y;
    }
    if (lane == 31) wsum[wid] = x;
    __syncthreads();
    if (wid == 0) {
        int w = wsum[lane];
        int xw = w;
        #pragma unroll
        for (int off = 1; off < 32; off <<= 1) {
            int y = __shfl_up_sync(0xFFFFFFFFu, xw, off);
            if (lane >= off) xw += y;
        }
        wsum[lane] = xw - w;
        if (lane == 31) g_bsum[blockIdx.x] = xw;
    }
    __syncthreads();
    int excl = wsum[wid] + (x - v);
    if (i < NN) g_rowptr[i] = excl;
}

__global__ void scan2_kernel() {
    int t = threadIdx.x;  // 64
    int lane = t & 31, wid = t >> 5;
    __shared__ int w0sum;
    int v = (t < SCAN_NBLK) ? g_bsum[t] : 0;
    int x = v;
    #pragma unroll
    for (int off = 1; off < 32; off <<= 1) {
        int y = __shfl_up_sync(0xFFFFFFFFu, x, off);
        if (lane >= off) x += y;
    }
    if (wid == 0 && lane == 31) w0sum = x;
    __syncthreads();
    int excl = x - v + (wid ? w0sum : 0);
    if (t < SCAN_NBLK) g_bsum[t] = excl;
    if (t == 0) g_rowptr[NN] = EE;
}

__global__ __launch_bounds__(1024) void scan3_kernel() {
    int i = blockIdx.x * 1024 + threadIdx.x;
    if (i < NN) {
        int v = g_rowptr[i] + g_bsum[blockIdx.x];
        g_rowptr[i] = v;
        g_wr[i] = v;
    }
}

__global__ void fill_csr_kernel(const int* __restrict__ src, const int* __restrict__ dst) {
    int e4 = blockIdx.x * blockDim.x + threadIdx.x;
    if (e4 * 4 < EE) {
        int4 d = ((const int4*)dst)[e4];
        int4 s = ((const int4*)src)[e4];
        g_csrc[atomicAdd(&g_wr[d.x], 1)] = s.x;
        g_csrc[atomicAdd(&g_wr[d.y], 1)] = s.y;
        g_csrc[atomicAdd(&g_wr[d.z], 1)] = s.z;
        g_csrc[atomicAdd(&g_wr[d.w], 1)] = s.w;
    }
}

// ---------------- fp16 tensor-core GEMM + fused el/er epilogue --------------
// C[M,128] = A[M,128] @ W[128,128]; fp16 inputs (converted on stage), fp32 accum.
// fp16 mantissa == tf32 mantissa (10 bits) -> same rounding error as tf32 path.
__device__ __forceinline__ uint32_t smem_u32(const void* p) {
    return (uint32_t)__cvta_generic_to_shared(p);
}

__device__ __forceinline__ void ldmatrix_x4(uint32_t* d, uint32_t addr) {
    asm volatile("ldmatrix.sync.aligned.m8n8.x4.shared.b16 {%0,%1,%2,%3}, [%4];"
                 : "=r"(d[0]), "=r"(d[1]), "=r"(d[2]), "=r"(d[3]) : "r"(addr));
}

__device__ __forceinline__ void ldmatrix_x4_trans(uint32_t* d, uint32_t addr) {
    asm volatile("ldmatrix.sync.aligned.m8n8.x4.trans.shared.b16 {%0,%1,%2,%3}, [%4];"
                 : "=r"(d[0]), "=r"(d[1]), "=r"(d[2]), "=r"(d[3]) : "r"(addr));
}

__device__ __forceinline__ void mma_f16(float* c, const uint32_t* a,
                                        uint32_t b0, uint32_t b1) {
    asm volatile(
        "mma.sync.aligned.m16n8k16.row.col.f32.f16.f16.f32 "
        "{%0,%1,%2,%3}, {%4,%5,%6,%7}, {%8,%9}, {%0,%1,%2,%3};"
        : "+f"(c[0]), "+f"(c[1]), "+f"(c[2]), "+f"(c[3])
        : "r"(a[0]), "r"(a[1]), "r"(a[2]), "r"(a[3]), "r"(b0), "r"(b1));
}

// block: 256 thr = 8 warps, 2(row)x4(col); tile 64 rows x 128 cols; k-chunk 64.
// smem rows padded to 136 halves (272B stride == 16 mod 128 -> ldmatrix conflict-free)
__global__ __launch_bounds__(256) void gemm_h16_kernel(
    const float* __restrict__ A, const float* __restrict__ W, __half* __restrict__ C,
    const float* __restrict__ al, const float* __restrict__ ar) {
    __shared__ __half As[64][136];
    __shared__ __half Wsh[64][136];
    __shared__ float s_el[64][8];
    __shared__ float s_er[64][8];
    int tid = threadIdx.x;
    int wid = tid >> 5;
    int lane = tid & 31;
    int g = lane >> 2;
    int tig = lane & 3;
    int warpRow = wid & 1;
    int warpCol = wid >> 1;
    int row0 = blockIdx.x << 6;

    float c[2][4][4];
    #pragma unroll
    for (int sm = 0; sm < 2; sm++)
        #pragma unroll
        for (int sn = 0; sn < 4; sn++)
            #pragma unroll
            for (int q = 0; q < 4; q++) c[sm][sn][q] = 0.f;

    for (int kc = 0; kc < 128; kc += 64) {
        // stage A chunk: 64 rows x 64 k (fp32 -> fp16)
        {
            int r = tid >> 2;          // 0..63
            int q = tid & 3;           // 16-col quarter
            int gr = row0 + r;
            #pragma unroll
            for (int i = 0; i < 4; i++) {
                float4 v = (gr < NN)
                    ? *(const float4*)&A[gr * 128 + kc + q * 16 + i * 4]
                    : make_float4(0.f, 0.f, 0.f, 0.f);
                *(__half2*)&As[r][q * 16 + i * 4]     = __floats2half2_rn(v.x, v.y);
                *(__half2*)&As[r][q * 16 + i * 4 + 2] = __floats2half2_rn(v.z, v.w);
            }
        }
        // stage W chunk: 64 k x 128 cols
        #pragma unroll
        for (int i = 0; i < 8; i++) {
            int idx = tid + (i << 8);       // 2048 float4 units
            int k = idx >> 5;
            int c4 = idx & 31;
            float4 v = *(const float4*)&W[(kc + k) * 128 + c4 * 4];
            *(__half2*)&Wsh[k][c4 * 4]     = __floats2half2_rn(v.x, v.y);
            *(__half2*)&Wsh[k][c4 * 4 + 2] = __floats2half2_rn(v.z, v.w);
        }
        __syncthreads();
        #pragma unroll
        for (int kk = 0; kk < 64; kk += 16) {
            uint32_t a[2][4], b[2][4];
            #pragma unroll
            for (int sm = 0; sm < 2; sm++) {
                int r = warpRow * 32 + sm * 16 + (lane & 15);
                ldmatrix_x4(a[sm], smem_u32(&As[r][kk + ((lane >> 4) << 3)]));
            }
            #pragma unroll
            for (int nb = 0; nb < 2; nb++) {
                int col = warpCol * 32 + nb * 16 + ((lane >> 4) << 3);
                ldmatrix_x4_trans(b[nb], smem_u32(&Wsh[kk + (lane & 15)][col]));
            }
            #pragma unroll
            for (int sm = 0; sm < 2; sm++)
                #pragma unroll
                for (int sn = 0; sn < 4; sn++)
                    mma_f16(c[sm][sn], a[sm],
                            b[sn >> 1][(sn & 1) * 2], b[sn >> 1][(sn & 1) * 2 + 1]);
        }
        __syncthreads();
    }

    // ---- store C (fp16) + compute el/er ----
    float alr[4][2], arr[4][2];
    #pragma unroll
    for (int sn = 0; sn < 4; sn++) {
        int col = warpCol * 32 + sn * 8 + tig * 2;
        alr[sn][0] = al[col];     alr[sn][1] = al[col + 1];
        arr[sn][0] = ar[col];     arr[sn][1] = ar[col + 1];
    }
    #pragma unroll
    for (int sm = 0; sm < 2; sm++) {
        int rbase = row0 + warpRow * 32 + sm * 16 + g;
        #pragma unroll
        for (int sn = 0; sn < 4; sn++) {
            int col = warpCol * 32 + sn * 8 + tig * 2;
            if (rbase < NN)
                *(__half2*)&C[rbase * 128 + col] =
                    __floats2half2_rn(c[sm][sn][0], c[sm][sn][1]);
            if (rbase + 8 < NN)
                *(__half2*)&C[(rbase + 8) * 128 + col] =
                    __floats2half2_rn(c[sm][sn][2], c[sm][sn][3]);
        }
        #pragma unroll
        for (int hh = 0; hh < 2; hh++) {
            #pragma unroll
            for (int ro = 0; ro < 2; ro++) {
                float pel = 0.f, per = 0.f;
                #pragma unroll
                for (int sni = 0; sni < 2; sni++) {
                    int sn = hh * 2 + sni;
                    #pragma unroll
                    for (int qq = 0; qq < 2; qq++) {
                        float cv = c[sm][sn][ro * 2 + qq];
                        pel = fmaf(cv, alr[sn][qq], pel);
                        per = fmaf(cv, arr[sn][qq], per);
                    }
                }
                pel += __shfl_xor_sync(0xFFFFFFFFu, pel, 1);
                pel += __shfl_xor_sync(0xFFFFFFFFu, pel, 2);
                per += __shfl_xor_sync(0xFFFFFFFFu, per, 1);
                per += __shfl_xor_sync(0xFFFFFFFFu, per, 2);
                if (tig == 0) {
                    int r = warpRow * 32 + sm * 16 + g + ro * 8;
                    int h = warpCol * 2 + hh;
                    s_el[r][h] = pel;
                    s_er[r][h] = per;
                }
            }
        }
    }
    __syncthreads();
    #pragma unroll
    for (int q = 0; q < 2; q++) {
        int idx = tid + (q << 8);
        int r = idx >> 3, h = idx & 7;
        if (row0 + r < NN) {
            g_el[(row0 + r) * 8 + h] = s_el[r][h];
            g_er[(row0 + r) * 8 + h] = s_er[r][h];
        }
    }
}

// ---------------- fused: edge-softmax aggregate + bias + LN + ReLU ----------
__global__ __launch_bounds__(256) void gat_agg_kernel(
    const __half* __restrict__ hp,
    const float* __restrict__ bias, const float* __restrict__ gamma,
    const float* __restrict__ beta, float* __restrict__ hout) {
    int n = blockIdx.x * 8 + (threadIdx.x >> 5);
    if (n >= NN) return;
    int lane = threadIdx.x & 31;
    int h = lane >> 2;
    float er_h = g_er[n * 8 + h];
    int beg = g_rowptr[n];
    int end = g_rowptr[n + 1];
    const uint2* __restrict__ hp2 = (const uint2*)hp;

    float ax = 0.f, ay = 0.f, az = 0.f, aw = 0.f, s = 0.f;
    int j = beg;
    for (; j + 8 <= end; j += 8) {
        int idx[8];
        #pragma unroll
        for (int u = 0; u < 8; u++) idx[u] = g_csrc[j + u];
        float e[8];
        #pragma unroll
        for (int u = 0; u < 8; u++) e[u] = g_el[idx[u] * 8 + h];
        uint2 v[8];
        #pragma unroll
        for (int u = 0; u < 8; u++) v[u] = hp2[idx[u] * 32 + lane];
        #pragma unroll
        for (int u = 0; u < 8; u++) {
            float ee = e[u] + er_h;
            ee = (ee > 0.f) ? ee : 0.2f * ee;
            float w = __expf(ee);
            s += w;
            float2 f0 = __half22float2(*(__half2*)&v[u].x);
            float2 f1 = __half22float2(*(__half2*)&v[u].y);
            ax = fmaf(w, f0.x, ax);
            ay = fmaf(w, f0.y, ay);
            az = fmaf(w, f1.x, az);
            aw = fmaf(w, f1.y, aw);
        }
    }
    for (; j + 4 <= end; j += 4) {
        int idx[4];
        #pragma unroll
        for (int u = 0; u < 4; u++) idx[u] = g_csrc[j + u];
        float e[4];
        #pragma unroll
        for (int u = 0; u < 4; u++) e[u] = g_el[idx[u] * 8 + h];
        uint2 v[4];
        #pragma unroll
        for (int u = 0; u < 4; u++) v[u] = hp2[idx[u] * 32 + lane];
        #pragma unroll
        for (int u = 0; u < 4; u++) {
            float ee = e[u] + er_h;
            ee = (ee > 0.f) ? ee : 0.2f * ee;
            float w = __expf(ee);
            s += w;
            float2 f0 = __half22float2(*(__half2*)&v[u].x);
            float2 f1 = __half22float2(*(__half2*)&v[u].y);
            ax = fmaf(w, f0.x, ax);
            ay = fmaf(w, f0.y, ay);
            az = fmaf(w, f1.x, az);
            aw = fmaf(w, f1.y, aw);
        }
    }
    for (; j < end; j++) {
        int s0 = g_csrc[j];
        float e0 = g_el[s0 * 8 + h] + er_h;
        e0 = (e0 > 0.f) ? e0 : 0.2f * e0;
        float w0 = __expf(e0);
        uint2 v0 = hp2[s0 * 32 + lane];
        s += w0;
        float2 f0 = __half22float2(*(__half2*)&v0.x);
        float2 f1 = __half22float2(*(__half2*)&v0.y);
        ax = fmaf(w0, f0.x, ax);
        ay = fmaf(w0, f0.y, ay);
        az = fmaf(w0, f1.x, az);
        aw = fmaf(w0, f1.y, aw);
    }

    float inv = 1.f / (s + 1e-16f);
    float4 b4  = ((const float4*)bias)[lane];
    float4 g4  = ((const float4*)gamma)[lane];
    float4 be4 = ((const float4*)beta)[lane];
    float ox = fmaf(ax, inv, b4.x);
    float oy = fmaf(ay, inv, b4.y);
    float oz = fmaf(az, inv, b4.z);
    float ow = fmaf(aw, inv, b4.w);

    float sum = (ox + oy) + (oz + ow);
    #pragma unroll
    for (int off = 16; off >= 1; off >>= 1) sum += __shfl_xor_sync(0xFFFFFFFFu, sum, off);
    float mu = sum * 0.0078125f;
    float dx = ox - mu, dy = oy - mu, dz = oz - mu, dw = ow - mu;
    float sq = (dx * dx + dy * dy) + (dz * dz + dw * dw);
    #pragma unroll
    for (int off = 16; off >= 1; off >>= 1) sq += __shfl_xor_sync(0xFFFFFFFFu, sq, off);
    float rstd = rsqrtf(sq * 0.0078125f + 1e-5f);
    float4 o;
    o.x = fmaxf(fmaf(dx * rstd, g4.x, be4.x), 0.f);
    o.y = fmaxf(fmaf(dy * rstd, g4.y, be4.y), 0.f);
    o.z = fmaxf(fmaf(dz * rstd, g4.z, be4.z), 0.f);
    o.w = fmaxf(fmaf(dw * rstd, g4.w, be4.w), 0.f);
    ((float4*)hout)[n * 32 + lane] = o;
}

// ---------------- final projection: out[N,40] = h[N,128] @ Wp + bp ----------
__global__ __launch_bounds__(160) void pred_kernel(
    const float* __restrict__ hfeat, const float* __restrict__ Wp,
    const float* __restrict__ bp, float* __restrict__ out) {
    __shared__ float Hs[64][68];
    __shared__ float Wsh[64][40];
    int tid = threadIdx.x;
    int ci = tid % 10;
    int j  = tid / 10;
    int n0 = blockIdx.x << 6;
    float acc[4][4];
    #pragma unroll
    for (int r = 0; r < 4; r++)
        #pragma unroll
        for (int c = 0; c < 4; c++) acc[r][c] = 0.f;

    for (int kc = 0; kc < 128; kc += 64) {
        for (int idx = tid; idx < 64 * 64; idx += 160) {
            int n = idx >> 6;
            int k = idx & 63;
            int gn = n0 + n;
            Hs[k][n] = (gn < NN) ? hfeat[gn * 128 + kc + k] : 0.f;
        }
        for (int idx = tid; idx < 64 * 40; idx += 160) {
            int k = idx / 40;
            int c = idx - k * 40;
            Wsh[k][c] = Wp[(kc + k) * 40 + c];
        }
        __syncthreads();
        #pragma unroll
        for (int k = 0; k < 64; k++) {
            float4 a = *(const float4*)&Hs[k][j * 4];
            float4 b = *(const float4*)&Wsh[k][ci * 4];
            float av[4] = {a.x, a.y, a.z, a.w};
            float bv[4] = {b.x, b.y, b.z, b.w};
            #pragma unroll
            for (int r = 0; r < 4; r++)
                #pragma unroll
                for (int c = 0; c < 4; c++)
                    acc[r][c] = fmaf(av[r], bv[c], acc[r][c]);
        }
        __syncthreads();
    }
    #pragma unroll
    for (int r = 0; r < 4; r++) {
        int gn = n0 + j * 4 + r;
        if (gn < NN) {
            #pragma unroll
            for (int c = 0; c < 4; c++)
                out[gn * CCOLS + ci * 4 + c] = acc[r][c] + bp[ci * 4 + c];
        }
    }
}

// ---------------- launch ----------------------------------------------------
extern "C" void kernel_launch(void* const* d_in, const int* in_sizes, int n_in,
                              void* d_out, int out_size) {
    const float* feats = (const float*)d_in[0];
    const int*   src   = (const int*)d_in[1];
    const int*   dst   = (const int*)d_in[2];
    const float* Ws    = (const float*)d_in[3];
    const float* al    = (const float*)d_in[4];
    const float* ar    = (const float*)d_in[5];
    const float* bias  = (const float*)d_in[6];
    const float* gamma = (const float*)d_in[7];
    const float* beta  = (const float*)d_in[8];
    const float* Wp    = (const float*)d_in[9];
    const float* bp    = (const float*)d_in[10];
    float* out = (float*)d_out;

    __half* hp;  cudaGetSymbolAddress((void**)&hp, g_hp);
    float* hbuf; cudaGetSymbolAddress((void**)&hbuf, g_hbuf);

    // CSR build (multi-kernel pipeline — no grid-wide spin barriers)
    zero_wr_kernel<<<(NN + 255) / 256, 256>>>();
    count_deg_kernel<<<(EE / 4 + 255) / 256, 256>>>(dst);
    scan1_kernel<<<SCAN_NBLK, 1024>>>();
    scan2_kernel<<<1, 64>>>();
    scan3_kernel<<<SCAN_NBLK, 1024>>>();
    fill_csr_kernel<<<(EE / 4 + 255) / 256, 256>>>(src, dst);

    const int gemm_blocks = (NN + 63) / 64;  // 782
    gemm_h16_kernel<<<gemm_blocks, 256>>>(feats, Ws, hp, al, ar);
    gat_agg_kernel<<<(NN + 7) / 8, 256>>>(hp, bias, gamma, beta, hbuf);

    gemm_h16_kernel<<<gemm_blocks, 256>>>(hbuf, Ws + 128 * 128, hp,
                                          al + 128, ar + 128);
    gat_agg_kernel<<<(NN + 7) / 8, 256>>>(hp, bias + 128, gamma + 128,
                                          beta + 128, hbuf);

    pred_kernel<<<gemm_blocks, 160>>>(hbuf, Wp, bp, out);
}

// round 8
// speedup vs baseline: 1.1000x; 1.0147x over previous
#include <cuda_runtime.h>
#include <cuda_fp16.h>
#include <cstdint>

#define NN 50000
#define EE 800000
#define HH 8
#define HD 128
#define CCOLS 40
#define SCAN_NBLK 49   // ceil(50000/1024)

// ---------------- scratch -------------------------------------------------
__device__ __half g_hp[NN * HD];     // fp16 projected features (gather payload)
__device__ float  g_hbuf[NN * HD];   // layer output / next-layer input (fp32)
__device__ float  g_el[NN * HH];
__device__ float  g_er[NN * HH];
__device__ int    g_rowptr[NN + 1];
__device__ int    g_wr[NN];
__device__ int    g_csrc[EE];
__device__ int    g_flags[SCAN_NBLK];   // lookback: status<<24 | value (EE < 2^24)

// ---------------- CSR build: memset + count + lookback-scan + fill ----------
// count 4 edges/thread via int4; also resets the scan flags (stream-ordered
// before the scan kernel runs).
__global__ void count_deg_kernel(const int* __restrict__ dst) {
    int e4 = blockIdx.x * blockDim.x + threadIdx.x;
    if (e4 < SCAN_NBLK) g_flags[e4] = 0;
    if (e4 * 4 < EE) {
        int4 d = ((const int4*)dst)[e4];
        atomicAdd(&g_wr[d.x], 1);
        atomicAdd(&g_wr[d.y], 1);
        atomicAdd(&g_wr[d.z], 1);
        atomicAdd(&g_wr[d.w], 1);
    }
}

__device__ __forceinline__ int block_excl_scan1024(int v, int& total) {
    __shared__ int wsum[33];
    int lane = threadIdx.x & 31, wid = threadIdx.x >> 5;
    int x = v;
    #pragma unroll
    for (int off = 1; off < 32; off <<= 1) {
        int y = __shfl_up_sync(0xFFFFFFFFu, x, off);
        if (lane >= off) x += y;
    }
    if (lane == 31) wsum[wid] = x;
    __syncthreads();
    if (wid == 0) {
        int w = wsum[lane];
        int xw = w;
        #pragma unroll
        for (int off = 1; off < 32; off <<= 1) {
            int y = __shfl_up_sync(0xFFFFFFFFu, xw, off);
            if (lane >= off) xw += y;
        }
        wsum[lane] = xw - w;
        if (lane == 31) wsum[32] = xw;
    }
    __syncthreads();
    total = wsum[32];
    return wsum[wid] + x - v;
}

// single-pass decoupled-lookback scan over g_wr -> g_rowptr (+ cursor init).
// Safe: blocks become resident in bid order, so a waiter's predecessor has
// always been scheduled (CUB single-pass invariant).
__global__ __launch_bounds__(1024) void scan_lookback_kernel() {
    __shared__ int s_excl;
    int t = threadIdx.x;
    int bid = blockIdx.x;
    int i = bid * 1024 + t;
    int v = (i < NN) ? g_wr[i] : 0;
    int total;
    int excl = block_excl_scan1024(v, total);

    if (t == 0) {
        if (bid == 0) {
            __threadfence();
            atomicExch(&g_flags[0], (2 << 24) | total);   // inclusive prefix ready
            s_excl = 0;
        } else {
            __threadfence();
            atomicExch(&g_flags[bid], (1 << 24) | total); // aggregate ready
            int run = 0;
            int j = bid - 1;
            while (j >= 0) {
                int f = atomicAdd(&g_flags[j], 0);
                int st = f >> 24;
                if (st == 0) continue;                    // predecessor not ready yet
                run += f & 0xFFFFFF;
                if (st == 2) break;                       // hit an inclusive prefix
                j--;
            }
            __threadfence();
            atomicExch(&g_flags[bid], (2 << 24) | (run + total));
            s_excl = run;
        }
    }
    __syncthreads();
    if (i < NN) {
        int val = s_excl + excl;
        g_rowptr[i] = val;
        g_wr[i] = val;    // write cursor for fill
    }
    if (bid == 0 && t == 0) g_rowptr[NN] = EE;
}

__global__ void fill_csr_kernel(const int* __restrict__ src, const int* __restrict__ dst) {
    int e4 = blockIdx.x * blockDim.x + threadIdx.x;
    if (e4 * 4 < EE) {
        int4 d = ((const int4*)dst)[e4];
        int4 s = ((const int4*)src)[e4];
        g_csrc[atomicAdd(&g_wr[d.x], 1)] = s.x;
        g_csrc[atomicAdd(&g_wr[d.y], 1)] = s.y;
        g_csrc[atomicAdd(&g_wr[d.z], 1)] = s.z;
        g_csrc[atomicAdd(&g_wr[d.w], 1)] = s.w;
    }
}

// ---------------- fp16 tensor-core GEMM + fused el/er epilogue --------------
__device__ __forceinline__ uint32_t smem_u32(const void* p) {
    return (uint32_t)__cvta_generic_to_shared(p);
}

__device__ __forceinline__ void ldmatrix_x4(uint32_t* d, uint32_t addr) {
    asm volatile("ldmatrix.sync.aligned.m8n8.x4.shared.b16 {%0,%1,%2,%3}, [%4];"
                 : "=r"(d[0]), "=r"(d[1]), "=r"(d[2]), "=r"(d[3]) : "r"(addr));
}

__device__ __forceinline__ void ldmatrix_x4_trans(uint32_t* d, uint32_t addr) {
    asm volatile("ldmatrix.sync.aligned.m8n8.x4.trans.shared.b16 {%0,%1,%2,%3}, [%4];"
                 : "=r"(d[0]), "=r"(d[1]), "=r"(d[2]), "=r"(d[3]) : "r"(addr));
}

__device__ __forceinline__ void mma_f16(float* c, const uint32_t* a,
                                        uint32_t b0, uint32_t b1) {
    asm volatile(
        "mma.sync.aligned.m16n8k16.row.col.f32.f16.f16.f32 "
        "{%0,%1,%2,%3}, {%4,%5,%6,%7}, {%8,%9}, {%0,%1,%2,%3};"
        : "+f"(c[0]), "+f"(c[1]), "+f"(c[2]), "+f"(c[3])
        : "r"(a[0]), "r"(a[1]), "r"(a[2]), "r"(a[3]), "r"(b0), "r"(b1));
}

__global__ __launch_bounds__(256) void gemm_h16_kernel(
    const float* __restrict__ A, const float* __restrict__ W, __half* __restrict__ C,
    const float* __restrict__ al, const float* __restrict__ ar) {
    __shared__ __half As[64][136];
    __shared__ __half Wsh[64][136];
    __shared__ float s_el[64][8];
    __shared__ float s_er[64][8];
    int tid = threadIdx.x;
    int wid = tid >> 5;
    int lane = tid & 31;
    int g = lane >> 2;
    int tig = lane & 3;
    int warpRow = wid & 1;
    int warpCol = wid >> 1;
    int row0 = blockIdx.x << 6;

    float c[2][4][4];
    #pragma unroll
    for (int sm = 0; sm < 2; sm++)
        #pragma unroll
        for (int sn = 0; sn < 4; sn++)
            #pragma unroll
            for (int q = 0; q < 4; q++) c[sm][sn][q] = 0.f;

    for (int kc = 0; kc < 128; kc += 64) {
        {
            int r = tid >> 2;
            int q = tid & 3;
            int gr = row0 + r;
            #pragma unroll
            for (int i = 0; i < 4; i++) {
                float4 v = (gr < NN)
                    ? *(const float4*)&A[gr * 128 + kc + q * 16 + i * 4]
                    : make_float4(0.f, 0.f, 0.f, 0.f);
                *(__half2*)&As[r][q * 16 + i * 4]     = __floats2half2_rn(v.x, v.y);
                *(__half2*)&As[r][q * 16 + i * 4 + 2] = __floats2half2_rn(v.z, v.w);
            }
        }
        #pragma unroll
        for (int i = 0; i < 8; i++) {
            int idx = tid + (i << 8);
            int k = idx >> 5;
            int c4 = idx & 31;
            float4 v = *(const float4*)&W[(kc + k) * 128 + c4 * 4];
            *(__half2*)&Wsh[k][c4 * 4]     = __floats2half2_rn(v.x, v.y);
            *(__half2*)&Wsh[k][c4 * 4 + 2] = __floats2half2_rn(v.z, v.w);
        }
        __syncthreads();
        #pragma unroll
        for (int kk = 0; kk < 64; kk += 16) {
            uint32_t a[2][4], b[2][4];
            #pragma unroll
            for (int sm = 0; sm < 2; sm++) {
                int r = warpRow * 32 + sm * 16 + (lane & 15);
                ldmatrix_x4(a[sm], smem_u32(&As[r][kk + ((lane >> 4) << 3)]));
            }
            #pragma unroll
            for (int nb = 0; nb < 2; nb++) {
                int col = warpCol * 32 + nb * 16 + ((lane >> 4) << 3);
                ldmatrix_x4_trans(b[nb], smem_u32(&Wsh[kk + (lane & 15)][col]));
            }
            #pragma unroll
            for (int sm = 0; sm < 2; sm++)
                #pragma unroll
                for (int sn = 0; sn < 4; sn++)
                    mma_f16(c[sm][sn], a[sm],
                            b[sn >> 1][(sn & 1) * 2], b[sn >> 1][(sn & 1) * 2 + 1]);
        }
        __syncthreads();
    }

    float alr[4][2], arr[4][2];
    #pragma unroll
    for (int sn = 0; sn < 4; sn++) {
        int col = warpCol * 32 + sn * 8 + tig * 2;
        alr[sn][0] = al[col];     alr[sn][1] = al[col + 1];
        arr[sn][0] = ar[col];     arr[sn][1] = ar[col + 1];
    }
    #pragma unroll
    for (int sm = 0; sm < 2; sm++) {
        int rbase = row0 + warpRow * 32 + sm * 16 + g;
        #pragma unroll
        for (int sn = 0; sn < 4; sn++) {
            int col = warpCol * 32 + sn * 8 + tig * 2;
            if (rbase < NN)
                *(__half2*)&C[rbase * 128 + col] =
                    __floats2half2_rn(c[sm][sn][0], c[sm][sn][1]);
            if (rbase + 8 < NN)
                *(__half2*)&C[(rbase + 8) * 128 + col] =
                    __floats2half2_rn(c[sm][sn][2], c[sm][sn][3]);
        }
        #pragma unroll
        for (int hh = 0; hh < 2; hh++) {
            #pragma unroll
            for (int ro = 0; ro < 2; ro++) {
                float pel = 0.f, per = 0.f;
                #pragma unroll
                for (int sni = 0; sni < 2; sni++) {
                    int sn = hh * 2 + sni;
                    #pragma unroll
                    for (int qq = 0; qq < 2; qq++) {
                        float cv = c[sm][sn][ro * 2 + qq];
                        pel = fmaf(cv, alr[sn][qq], pel);
                        per = fmaf(cv, arr[sn][qq], per);
                    }
                }
                pel += __shfl_xor_sync(0xFFFFFFFFu, pel, 1);
                pel += __shfl_xor_sync(0xFFFFFFFFu, pel, 2);
                per += __shfl_xor_sync(0xFFFFFFFFu, per, 1);
                per += __shfl_xor_sync(0xFFFFFFFFu, per, 2);
                if (tig == 0) {
                    int r = warpRow * 32 + sm * 16 + g + ro * 8;
                    int h = warpCol * 2 + hh;
                    s_el[r][h] = pel;
                    s_er[r][h] = per;
                }
            }
        }
    }
    __syncthreads();
    #pragma unroll
    for (int q = 0; q < 2; q++) {
        int idx = tid + (q << 8);
        int r = idx >> 3, h = idx & 7;
        if (row0 + r < NN) {
            g_el[(row0 + r) * 8 + h] = s_el[r][h];
            g_er[(row0 + r) * 8 + h] = s_er[r][h];
        }
    }
}

// ---------------- fused: edge-softmax aggregate + bias + LN + ReLU ----------
__global__ __launch_bounds__(256) void gat_agg_kernel(
    const __half* __restrict__ hp,
    const float* __restrict__ bias, const float* __restrict__ gamma,
    const float* __restrict__ beta, float* __restrict__ hout) {
    int n = blockIdx.x * 8 + (threadIdx.x >> 5);
    if (n >= NN) return;
    int lane = threadIdx.x & 31;
    int h = lane >> 2;
    float er_h = g_er[n * 8 + h];
    int beg = g_rowptr[n];
    int end = g_rowptr[n + 1];
    const uint2* __restrict__ hp2 = (const uint2*)hp;

    float ax = 0.f, ay = 0.f, az = 0.f, aw = 0.f, s = 0.f;
    int j = beg;
    for (; j + 8 <= end; j += 8) {
        int idx[8];
        #pragma unroll
        for (int u = 0; u < 8; u++) idx[u] = g_csrc[j + u];
        float e[8];
        #pragma unroll
        for (int u = 0; u < 8; u++) e[u] = g_el[idx[u] * 8 + h];
        uint2 v[8];
        #pragma unroll
        for (int u = 0; u < 8; u++) v[u] = hp2[idx[u] * 32 + lane];
        #pragma unroll
        for (int u = 0; u < 8; u++) {
            float ee = e[u] + er_h;
            ee = (ee > 0.f) ? ee : 0.2f * ee;
            float w = __expf(ee);
            s += w;
            float2 f0 = __half22float2(*(__half2*)&v[u].x);
            float2 f1 = __half22float2(*(__half2*)&v[u].y);
            ax = fmaf(w, f0.x, ax);
            ay = fmaf(w, f0.y, ay);
            az = fmaf(w, f1.x, az);
            aw = fmaf(w, f1.y, aw);
        }
    }
    for (; j + 4 <= end; j += 4) {
        int idx[4];
        #pragma unroll
        for (int u = 0; u < 4; u++) idx[u] = g_csrc[j + u];
        float e[4];
        #pragma unroll
        for (int u = 0; u < 4; u++) e[u] = g_el[idx[u] * 8 + h];
        uint2 v[4];
        #pragma unroll
        for (int u = 0; u < 4; u++) v[u] = hp2[idx[u] * 32 + lane];
        #pragma unroll
        for (int u = 0; u < 4; u++) {
            float ee = e[u] + er_h;
            ee = (ee > 0.f) ? ee : 0.2f * ee;
            float w = __expf(ee);
            s += w;
            float2 f0 = __half22float2(*(__half2*)&v[u].x);
            float2 f1 = __half22float2(*(__half2*)&v[u].y);
            ax = fmaf(w, f0.x, ax);
            ay = fmaf(w, f0.y, ay);
            az = fmaf(w, f1.x, az);
            aw = fmaf(w, f1.y, aw);
        }
    }
    for (; j < end; j++) {
        int s0 = g_csrc[j];
        float e0 = g_el[s0 * 8 + h] + er_h;
        e0 = (e0 > 0.f) ? e0 : 0.2f * e0;
        float w0 = __expf(e0);
        uint2 v0 = hp2[s0 * 32 + lane];
        s += w0;
        float2 f0 = __half22float2(*(__half2*)&v0.x);
        float2 f1 = __half22float2(*(__half2*)&v0.y);
        ax = fmaf(w0, f0.x, ax);
        ay = fmaf(w0, f0.y, ay);
        az = fmaf(w0, f1.x, az);
        aw = fmaf(w0, f1.y, aw);
    }

    float inv = 1.f / (s + 1e-16f);
    float4 b4  = ((const float4*)bias)[lane];
    float4 g4  = ((const float4*)gamma)[lane];
    float4 be4 = ((const float4*)beta)[lane];
    float ox = fmaf(ax, inv, b4.x);
    float oy = fmaf(ay, inv, b4.y);
    float oz = fmaf(az, inv, b4.z);
    float ow = fmaf(aw, inv, b4.w);

    float sum = (ox + oy) + (oz + ow);
    #pragma unroll
    for (int off = 16; off >= 1; off >>= 1) sum += __shfl_xor_sync(0xFFFFFFFFu, sum, off);
    float mu = sum * 0.0078125f;
    float dx = ox - mu, dy = oy - mu, dz = oz - mu, dw = ow - mu;
    float sq = (dx * dx + dy * dy) + (dz * dz + dw * dw);
    #pragma unroll
    for (int off = 16; off >= 1; off >>= 1) sq += __shfl_xor_sync(0xFFFFFFFFu, sq, off);
    float rstd = rsqrtf(sq * 0.0078125f + 1e-5f);
    float4 o;
    o.x = fmaxf(fmaf(dx * rstd, g4.x, be4.x), 0.f);
    o.y = fmaxf(fmaf(dy * rstd, g4.y, be4.y), 0.f);
    o.z = fmaxf(fmaf(dz * rstd, g4.z, be4.z), 0.f);
    o.w = fmaxf(fmaf(dw * rstd, g4.w, be4.w), 0.f);
    ((float4*)hout)[n * 32 + lane] = o;
}

// ---------------- final projection: out[N,40] = h[N,128] @ Wp + bp ----------
__global__ __launch_bounds__(160) void pred_kernel(
    const float* __restrict__ hfeat, const float* __restrict__ Wp,
    const float* __restrict__ bp, float* __restrict__ out) {
    __shared__ float Hs[64][68];
    __shared__ float Wsh[64][40];
    int tid = threadIdx.x;
    int ci = tid % 10;
    int j  = tid / 10;
    int n0 = blockIdx.x << 6;
    float acc[4][4];
    #pragma unroll
    for (int r = 0; r < 4; r++)
        #pragma unroll
        for (int c = 0; c < 4; c++) acc[r][c] = 0.f;

    for (int kc = 0; kc < 128; kc += 64) {
        for (int idx = tid; idx < 64 * 64; idx += 160) {
            int n = idx >> 6;
            int k = idx & 63;
            int gn = n0 + n;
            Hs[k][n] = (gn < NN) ? hfeat[gn * 128 + kc + k] : 0.f;
        }
        for (int idx = tid; idx < 64 * 40; idx += 160) {
            int k = idx / 40;
            int c = idx - k * 40;
            Wsh[k][c] = Wp[(kc + k) * 40 + c];
        }
        __syncthreads();
        #pragma unroll
        for (int k = 0; k < 64; k++) {
            float4 a = *(const float4*)&Hs[k][j * 4];
            float4 b = *(const float4*)&Wsh[k][ci * 4];
            float av[4] = {a.x, a.y, a.z, a.w};
            float bv[4] = {b.x, b.y, b.z, b.w};
            #pragma unroll
            for (int r = 0; r < 4; r++)
                #pragma unroll
                for (int c = 0; c < 4; c++)
                    acc[r][c] = fmaf(av[r], bv[c], acc[r][c]);
        }
        __syncthreads();
    }
    #pragma unroll
    for (int r = 0; r < 4; r++) {
        int gn = n0 + j * 4 + r;
        if (gn < NN) {
            #pragma unroll
            for (int c = 0; c < 4; c++)
                out[gn * CCOLS + ci * 4 + c] = acc[r][c] + bp[ci * 4 + c];
        }
    }
}

// ---------------- launch ----------------------------------------------------
extern "C" void kernel_launch(void* const* d_in, const int* in_sizes, int n_in,
                              void* d_out, int out_size) {
    const float* feats = (const float*)d_in[0];
    const int*   src   = (const int*)d_in[1];
    const int*   dst   = (const int*)d_in[2];
    const float* Ws    = (const float*)d_in[3];
    const float* al    = (const float*)d_in[4];
    const float* ar    = (const float*)d_in[5];
    const float* bias  = (const float*)d_in[6];
    const float* gamma = (const float*)d_in[7];
    const float* beta  = (const float*)d_in[8];
    const float* Wp    = (const float*)d_in[9];
    const float* bp    = (const float*)d_in[10];
    float* out = (float*)d_out;

    __half* hp;  cudaGetSymbolAddress((void**)&hp, g_hp);
    float* hbuf; cudaGetSymbolAddress((void**)&hbuf, g_hbuf);
    int* wr;     cudaGetSymbolAddress((void**)&wr, g_wr);

    static cudaStream_t s2 = nullptr;
    static cudaEvent_t evFork = nullptr, evJoin = nullptr;
    if (s2 == nullptr) {
        cudaStreamCreateWithFlags(&s2, cudaStreamNonBlocking);
        cudaEventCreateWithFlags(&evFork, cudaEventDisableTiming);
        cudaEventCreateWithFlags(&evJoin, cudaEventDisableTiming);
    }

    // fork: CSR chain (ordinary bounded kernels) on s2, concurrent with the
    // layer-0 GEMM on the main stream.
    cudaEventRecord(evFork, 0);
    cudaStreamWaitEvent(s2, evFork, 0);
    cudaMemsetAsync(wr, 0, NN * sizeof(int), s2);
    count_deg_kernel<<<(EE / 4 + 255) / 256, 256, 0, s2>>>(dst);
    scan_lookback_kernel<<<SCAN_NBLK, 1024, 0, s2>>>();
    fill_csr_kernel<<<(EE / 4 + 255) / 256, 256, 0, s2>>>(src, dst);
    cudaEventRecord(evJoin, s2);

    const int gemm_blocks = (NN + 63) / 64;  // 782
    gemm_h16_kernel<<<gemm_blocks, 256>>>(feats, Ws, hp, al, ar);
    cudaStreamWaitEvent(0, evJoin, 0);       // join before aggregation
    gat_agg_kernel<<<(NN + 7) / 8, 256>>>(hp, bias, gamma, beta, hbuf);

    gemm_h16_kernel<<<gemm_blocks, 256>>>(hbuf, Ws + 128 * 128, hp,
                                          al + 128, ar + 128);
    gat_agg_kernel<<<(NN + 7) / 8, 256>>>(hp, bias + 128, gamma + 128,
                                          beta + 128, hbuf);

    pred_kernel<<<gemm_blocks, 160>>>(hbuf, Wp, bp, out);
}